// round 6
// baseline (speedup 1.0000x reference)
#include <cuda_runtime.h>
#include <cuda_bf16.h>
#include <cstdint>

// Problem constants: B=8, T=1024, C=768, H=12, HD=64
__device__ float g_q[6291456];
__device__ float g_k[6291456];
__device__ float g_v[6291456];
__device__ float g_y[6291456];

// ---------------------------------------------------------------------------
// helpers
// ---------------------------------------------------------------------------
__device__ __forceinline__ float to_tf32(float x) {
    uint32_t u;
    asm("cvt.rna.tf32.f32 %0, %1;" : "=r"(u) : "f"(x));
    return __uint_as_float(u);
}
__device__ __forceinline__ uint32_t tf32b(float x) {
    uint32_t u;
    asm("cvt.rna.tf32.f32 %0, %1;" : "=r"(u) : "f"(x));
    return u;
}
__device__ __forceinline__ void mma_tf32(float* c, const uint32_t* a, const uint32_t* b) {
    asm volatile(
        "mma.sync.aligned.m16n8k8.row.col.f32.tf32.tf32.f32 "
        "{%0,%1,%2,%3},{%4,%5,%6,%7},{%8,%9},{%0,%1,%2,%3};"
        : "+f"(c[0]), "+f"(c[1]), "+f"(c[2]), "+f"(c[3])
        : "r"(a[0]), "r"(a[1]), "r"(a[2]), "r"(a[3]), "r"(b[0]), "r"(b[1]));
}
__device__ __forceinline__ uint32_t smem_u32(const void* p) {
    return (uint32_t)__cvta_generic_to_shared(p);
}
#define CP_ASYNC16(dst, src) \
    asm volatile("cp.async.cg.shared.global [%0], [%1], 16;\n" :: "r"(dst), "l"(src))
#define CP_COMMIT() asm volatile("cp.async.commit_group;\n")
#define CP_WAIT(N)  asm volatile("cp.async.wait_group %0;\n" :: "n"(N))

// ---------------------------------------------------------------------------
// TF32 GEMM v2: block tile 128x128, 8 warps (2m x 4n), warp tile 64x32,
// K-step 16, 2-stage cp.async double buffering, K = 768 (48 steps).
//   As pitch 20  -> A-frag banks (20g+tg)%32 bijective, conflict-free
//   Bs pitch 136 -> B-frag banks (8tg+g)%32 bijective, conflict-free
// __launch_bounds__(256,2) caps regs at 128 -> 16 warps/SM.
// ---------------------------------------------------------------------------
#define GEMM128_LOAD(S, K0, APTR, LDA, BPTR, LDB)                               \
    _Pragma("unroll")                                                           \
    for (int i = 0; i < 2; i++) {                                               \
        int r = a_r + i * 64;                                                   \
        CP_ASYNC16(smem_u32(&As[S][r][a_c]),                                    \
                   (APTR) + (size_t)(m0 + r) * (LDA) + (K0) + a_c);             \
    }                                                                           \
    _Pragma("unroll")                                                           \
    for (int i = 0; i < 2; i++) {                                               \
        int r = b_r + i * 8;                                                    \
        CP_ASYNC16(smem_u32(&Bs[S][r][b_c]),                                    \
                   (BPTR) + (size_t)((K0) + r) * (LDB) + n0 + b_c);             \
    }                                                                           \
    CP_COMMIT();

#define GEMM128_BODY(APTR, LDA, BPTR, LDB)                                      \
    __shared__ float As[2][128][20];                                            \
    __shared__ float Bs[2][16][136];                                            \
    const int tid  = threadIdx.x;                                               \
    const int lane = tid & 31;                                                  \
    const int wid  = tid >> 5;                                                  \
    const int warp_m = wid & 1, warp_n = wid >> 1;                              \
    const int g = lane >> 2, tg = lane & 3;                                     \
    const int m0 = blockIdx.y * 128, n0 = blockIdx.x * 128;                     \
    const int a_r = tid >> 2, a_c = (tid & 3) * 4;                              \
    const int b_r = tid >> 5, b_c = (tid & 31) * 4;                             \
    float acc[4][4][4] = {};                                                    \
    GEMM128_LOAD(0, 0, APTR, LDA, BPTR, LDB)                                    \
    for (int step = 0; step < 48; step++) {                                     \
        const int s = step & 1;                                                 \
        if (step + 1 < 48) {                                                    \
            GEMM128_LOAD(s ^ 1, (step + 1) * 16, APTR, LDA, BPTR, LDB)          \
            CP_WAIT(1);                                                         \
        } else {                                                                \
            CP_WAIT(0);                                                         \
        }                                                                       \
        __syncthreads();                                                        \
        _Pragma("unroll")                                                       \
        for (int ks = 0; ks < 2; ks++) {                                        \
            const int kk = ks * 8;                                              \
            uint32_t afr[4][4], bfr[4][2];                                      \
            _Pragma("unroll")                                                   \
            for (int mt = 0; mt < 4; mt++) {                                    \
                const int rb = warp_m * 64 + mt * 16;                           \
                afr[mt][0] = tf32b(As[s][rb + g][kk + tg]);                     \
                afr[mt][1] = tf32b(As[s][rb + g + 8][kk + tg]);                 \
                afr[mt][2] = tf32b(As[s][rb + g][kk + tg + 4]);                 \
                afr[mt][3] = tf32b(As[s][rb + g + 8][kk + tg + 4]);             \
            }                                                                   \
            _Pragma("unroll")                                                   \
            for (int nt = 0; nt < 4; nt++) {                                    \
                const int cb = warp_n * 32 + nt * 8;                            \
                bfr[nt][0] = tf32b(Bs[s][kk + tg][cb + g]);                     \
                bfr[nt][1] = tf32b(Bs[s][kk + tg + 4][cb + g]);                 \
            }                                                                   \
            _Pragma("unroll")                                                   \
            for (int mt = 0; mt < 4; mt++)                                      \
                _Pragma("unroll")                                               \
                for (int nt = 0; nt < 4; nt++)                                  \
                    mma_tf32(acc[mt][nt], afr[mt], bfr[nt]);                    \
        }                                                                       \
        __syncthreads();                                                        \
    }

// ---------------------------------------------------------------------------
// Kernel 1: QKV GEMM (M=8192, N=2304, K=768), scatter epilogue into
// q/k/v [B,H,T,64] with bias.
// ---------------------------------------------------------------------------
__global__ __launch_bounds__(256, 2) void gemm_qkv_tc(
    const float* __restrict__ x, const float* __restrict__ w,
    const float* __restrict__ bias)
{
    GEMM128_BODY(x, 768, w, 2304)

#pragma unroll
    for (int mt = 0; mt < 4; mt++) {
#pragma unroll
        for (int nt = 0; nt < 4; nt++) {
#pragma unroll
            for (int e = 0; e < 4; e++) {
                int m = m0 + warp_m * 64 + mt * 16 + g + (e >> 1) * 8;
                int n = n0 + warp_n * 32 + nt * 8 + 2 * tg + (e & 1);
                float v = acc[mt][nt][e] + bias[n];
                int bb = m >> 10, t = m & 1023;
                int which = n / 768;
                int c = n - which * 768;
                int hh = c >> 6, d = c & 63;
                float* dst = (which == 0) ? g_q : (which == 1) ? g_k : g_v;
                dst[((((size_t)bb * 12 + hh) << 10) + t) * 64 + d] = v;
            }
        }
    }
}

// ---------------------------------------------------------------------------
// Kernel 3: output projection (M=8192, N=768, K=768), reads g_y -> d_out.
// ---------------------------------------------------------------------------
__global__ __launch_bounds__(256, 2) void gemm_proj_tc(
    const float* __restrict__ w, const float* __restrict__ bias,
    float* __restrict__ out)
{
    GEMM128_BODY(g_y, 768, w, 768)

#pragma unroll
    for (int mt = 0; mt < 4; mt++) {
#pragma unroll
        for (int nt = 0; nt < 4; nt++) {
#pragma unroll
            for (int e = 0; e < 4; e++) {
                int m = m0 + warp_m * 64 + mt * 16 + g + (e >> 1) * 8;
                int n = n0 + warp_n * 32 + nt * 8 + 2 * tg + (e & 1);
                out[(size_t)m * 768 + n] = acc[mt][nt][e] + bias[n];
            }
        }
    }
}

// ---------------------------------------------------------------------------
// Kernel 2: causal flash attention with TF32 tensor cores (unchanged, R3).
// ---------------------------------------------------------------------------
__global__ __launch_bounds__(256) void attn_tc_kernel()
{
    __shared__ float Qs[64][68];
    __shared__ float Ks[32][68];
    __shared__ float Vs[32][72];
    __shared__ float Ps[64][36];
    __shared__ float s_m[64], s_l[64], s_f[64];

    const int tid = threadIdx.x;
    const int lane = tid & 31;
    const int wid = tid >> 5;
    const int warp_m = wid >> 1, warp_n = wid & 1;
    const int g = lane >> 2, tg = lane & 3;
    const int qi = blockIdx.x, bh = blockIdx.y;
    const int q0 = qi * 64;
    const float* qb = g_q + (size_t)bh * 65536;
    const float* kb = g_k + (size_t)bh * 65536;
    const float* vb = g_v + (size_t)bh * 65536;
    const int mr = warp_m * 16;

#pragma unroll
    for (int r = 0; r < 4; r++) {
        int idx = tid + r * 256;
        int q = idx >> 4, d4 = (idx & 15) * 4;
        float4 v4 = *(const float4*)(qb + (size_t)(q0 + q) * 64 + d4);
        float* dst = &Qs[q][d4];
        dst[0] = to_tf32(v4.x); dst[1] = to_tf32(v4.y);
        dst[2] = to_tf32(v4.z); dst[3] = to_tf32(v4.w);
    }
    if (tid < 64) { s_m[tid] = -1e30f; s_l[tid] = 0.0f; }

    float acc_o[4][4] = {};

    const int ktiles = 2 * qi + 2;
    for (int kt = 0; kt < ktiles; kt++) {
        const int k0 = kt * 32;

        float4 kv[2], vv[2];
#pragma unroll
        for (int r = 0; r < 2; r++) {
            int idx = tid + r * 256;
            int kk = idx >> 4, d4 = (idx & 15) * 4;
            kv[r] = *(const float4*)(kb + (size_t)(k0 + kk) * 64 + d4);
            vv[r] = *(const float4*)(vb + (size_t)(k0 + kk) * 64 + d4);
        }
        __syncthreads();
#pragma unroll
        for (int r = 0; r < 2; r++) {
            int idx = tid + r * 256;
            int kk = idx >> 4, d4 = (idx & 15) * 4;
            float* kd = &Ks[kk][d4];
            kd[0] = to_tf32(kv[r].x); kd[1] = to_tf32(kv[r].y);
            kd[2] = to_tf32(kv[r].z); kd[3] = to_tf32(kv[r].w);
            float* vd = &Vs[kk][d4];
            vd[0] = to_tf32(vv[r].x); vd[1] = to_tf32(vv[r].y);
            vd[2] = to_tf32(vv[r].z); vd[3] = to_tf32(vv[r].w);
        }
        __syncthreads();

        float acc_s[2][4] = {};
#pragma unroll
        for (int ks = 0; ks < 8; ks++) {
            const int kk = ks * 8;
            uint32_t afr[4];
            afr[0] = __float_as_uint(Qs[mr + g][kk + tg]);
            afr[1] = __float_as_uint(Qs[mr + g + 8][kk + tg]);
            afr[2] = __float_as_uint(Qs[mr + g][kk + tg + 4]);
            afr[3] = __float_as_uint(Qs[mr + g + 8][kk + tg + 4]);
#pragma unroll
            for (int nt = 0; nt < 2; nt++) {
                const int nc = warp_n * 16 + nt * 8;
                uint32_t bfr[2];
                bfr[0] = __float_as_uint(Ks[nc + g][kk + tg]);
                bfr[1] = __float_as_uint(Ks[nc + g][kk + tg + 4]);
                mma_tf32(acc_s[nt], afr, bfr);
            }
        }
#pragma unroll
        for (int nt = 0; nt < 2; nt++) {
            const int nc = warp_n * 16 + nt * 8;
#pragma unroll
            for (int e = 0; e < 4; e++) {
                int row = mr + g + (e >> 1) * 8;
                int col = nc + 2 * tg + (e & 1);
                int qg = q0 + row, kg = k0 + col;
                Ps[row][col] = (kg > qg) ? -1e30f : acc_s[nt][e] * 0.125f;
            }
        }
        __syncthreads();

        {
            const int row = tid >> 2, sub = tid & 3;
            float mold = s_m[row];
            float mt = mold;
            float vals[8];
#pragma unroll
            for (int j = 0; j < 8; j++) {
                vals[j] = Ps[row][sub * 8 + j];
                mt = fmaxf(mt, vals[j]);
            }
            mt = fmaxf(mt, __shfl_xor_sync(0xffffffffu, mt, 1));
            mt = fmaxf(mt, __shfl_xor_sync(0xffffffffu, mt, 2));
            float ls = 0.0f;
#pragma unroll
            for (int j = 0; j < 8; j++) {
                float p = __expf(vals[j] - mt);
                Ps[row][sub * 8 + j] = to_tf32(p);
                ls += p;
            }
            ls += __shfl_xor_sync(0xffffffffu, ls, 1);
            ls += __shfl_xor_sync(0xffffffffu, ls, 2);
            if (sub == 0) {
                float f = __expf(mold - mt);
                s_m[row] = mt;
                s_l[row] = s_l[row] * f + ls;
                s_f[row] = f;
            }
        }
        __syncthreads();

        float f0 = s_f[mr + g], f1 = s_f[mr + g + 8];
#pragma unroll
        for (int nt = 0; nt < 4; nt++) {
            acc_o[nt][0] *= f0; acc_o[nt][1] *= f0;
            acc_o[nt][2] *= f1; acc_o[nt][3] *= f1;
        }
#pragma unroll
        for (int ks = 0; ks < 4; ks++) {
            const int kk = ks * 8;
            uint32_t afr[4];
            afr[0] = __float_as_uint(Ps[mr + g][kk + tg]);
            afr[1] = __float_as_uint(Ps[mr + g + 8][kk + tg]);
            afr[2] = __float_as_uint(Ps[mr + g][kk + tg + 4]);
            afr[3] = __float_as_uint(Ps[mr + g + 8][kk + tg + 4]);
#pragma unroll
            for (int nt = 0; nt < 4; nt++) {
                const int nc = warp_n * 32 + nt * 8;
                uint32_t bfr[2];
                bfr[0] = __float_as_uint(Vs[kk + tg][nc + g]);
                bfr[1] = __float_as_uint(Vs[kk + tg + 4][nc + g]);
                mma_tf32(acc_o[nt], afr, bfr);
            }
        }
    }

    const int b = bh / 12, h = bh - b * 12;
    float inv0 = 1.0f / s_l[mr + g];
    float inv1 = 1.0f / s_l[mr + g + 8];
    const int t0 = q0 + mr + g, t1 = t0 + 8;
#pragma unroll
    for (int nt = 0; nt < 4; nt++) {
        int col = warp_n * 32 + nt * 8 + 2 * tg;
        float* d0 = g_y + ((size_t)(b * 1024 + t0)) * 768 + h * 64 + col;
        float* d1 = g_y + ((size_t)(b * 1024 + t1)) * 768 + h * 64 + col;
        *(float2*)d0 = make_float2(acc_o[nt][0] * inv0, acc_o[nt][1] * inv0);
        *(float2*)d1 = make_float2(acc_o[nt][2] * inv1, acc_o[nt][3] * inv1);
    }
}

// ---------------------------------------------------------------------------
extern "C" void kernel_launch(void* const* d_in, const int* in_sizes, int n_in,
                              void* d_out, int out_size)
{
    const float* x      = (const float*)d_in[0];
    const float* w_attn = (const float*)d_in[1];
    const float* b_attn = (const float*)d_in[2];
    const float* w_proj = (const float*)d_in[3];
    const float* b_proj = (const float*)d_in[4];
    float* out = (float*)d_out;

    gemm_qkv_tc<<<dim3(18, 64), 256>>>(x, w_attn, b_attn);
    attn_tc_kernel<<<dim3(16, 96), 256>>>();
    gemm_proj_tc<<<dim3(6, 64), 256>>>(w_proj, b_proj, out);
}

// round 7
// speedup vs baseline: 1.5073x; 1.5073x over previous
#include <cuda_runtime.h>
#include <cuda_bf16.h>
#include <cstdint>

// Problem constants: B=8, T=1024, C=768, H=12, HD=64
__device__ float g_q[6291456];
__device__ float g_k[6291456];
__device__ float g_v[6291456];
__device__ float g_y[6291456];
// Pre-rounded (tf32) copies of inputs
__device__ float g_x[6291456];
__device__ float g_wa[1769472];   // 768*2304
__device__ float g_wp[589824];    // 768*768

// ---------------------------------------------------------------------------
// helpers
// ---------------------------------------------------------------------------
__device__ __forceinline__ float to_tf32(float x) {
    uint32_t u;
    asm("cvt.rna.tf32.f32 %0, %1;" : "=r"(u) : "f"(x));
    return __uint_as_float(u);
}
__device__ __forceinline__ void mma_tf32(float* c, const uint32_t* a, const uint32_t* b) {
    asm volatile(
        "mma.sync.aligned.m16n8k8.row.col.f32.tf32.tf32.f32 "
        "{%0,%1,%2,%3},{%4,%5,%6,%7},{%8,%9},{%0,%1,%2,%3};"
        : "+f"(c[0]), "+f"(c[1]), "+f"(c[2]), "+f"(c[3])
        : "r"(a[0]), "r"(a[1]), "r"(a[2]), "r"(a[3]), "r"(b[0]), "r"(b[1]));
}
__device__ __forceinline__ uint32_t smem_u32(const void* p) {
    return (uint32_t)__cvta_generic_to_shared(p);
}
#define CP_ASYNC16(dst, src) \
    asm volatile("cp.async.cg.shared.global [%0], [%1], 16;\n" :: "r"(dst), "l"(src))
#define CP_COMMIT() asm volatile("cp.async.commit_group;\n")
#define CP_WAIT(N)  asm volatile("cp.async.wait_group %0;\n" :: "n"(N))

// ---------------------------------------------------------------------------
// Kernel 0: pre-round x, w_attn, w_proj to tf32 (removes all cvt from the
// GEMM hot loops).  One float4 per thread over the concatenated ranges.
//   x: 1572864 f4 | wa: 442368 f4 | wp: 147456 f4   -> 2162688 f4 total
// ---------------------------------------------------------------------------
__global__ __launch_bounds__(256) void preround_kernel(
    const float* __restrict__ x, const float* __restrict__ wa,
    const float* __restrict__ wp)
{
    long i = (long)blockIdx.x * 256 + threadIdx.x;
    const float4* src;
    float4* dst;
    if (i < 1572864)      { src = (const float4*)x  + i;            dst = (float4*)g_x  + i; }
    else if (i < 2015232) { src = (const float4*)wa + (i - 1572864); dst = (float4*)g_wa + (i - 1572864); }
    else                  { src = (const float4*)wp + (i - 2015232); dst = (float4*)g_wp + (i - 2015232); }
    float4 v = *src;
    v.x = to_tf32(v.x); v.y = to_tf32(v.y);
    v.z = to_tf32(v.z); v.w = to_tf32(v.w);
    *dst = v;
}

// ---------------------------------------------------------------------------
// TF32 GEMM v3: block tile 128x128, 8 warps (2m x 4n), warp tile 64x32,
// K-step 16, 2-stage cp.async.  Data is pre-rounded -> NO cvt in the loop.
//   As pitch 20  -> A-frag banks (20g+tg)%32 bijective, conflict-free
//   Bs pitch 136 -> B-frag banks (8tg+g)%32 bijective, conflict-free
// ---------------------------------------------------------------------------
#define GEMM128_LOAD(S, K0, APTR, LDA, BPTR, LDB)                               \
    _Pragma("unroll")                                                           \
    for (int i = 0; i < 2; i++) {                                               \
        int r = a_r + i * 64;                                                   \
        CP_ASYNC16(smem_u32(&As[S][r][a_c]),                                    \
                   (APTR) + (size_t)(m0 + r) * (LDA) + (K0) + a_c);             \
    }                                                                           \
    _Pragma("unroll")                                                           \
    for (int i = 0; i < 2; i++) {                                               \
        int r = b_r + i * 8;                                                    \
        CP_ASYNC16(smem_u32(&Bs[S][r][b_c]),                                    \
                   (BPTR) + (size_t)((K0) + r) * (LDB) + n0 + b_c);             \
    }                                                                           \
    CP_COMMIT();

#define GEMM128_BODY(APTR, LDA, BPTR, LDB)                                      \
    __shared__ float As[2][128][20];                                            \
    __shared__ float Bs[2][16][136];                                            \
    const int tid  = threadIdx.x;                                               \
    const int lane = tid & 31;                                                  \
    const int wid  = tid >> 5;                                                  \
    const int warp_m = wid & 1, warp_n = wid >> 1;                              \
    const int g = lane >> 2, tg = lane & 3;                                     \
    const int m0 = blockIdx.y * 128, n0 = blockIdx.x * 128;                     \
    const int a_r = tid >> 2, a_c = (tid & 3) * 4;                              \
    const int b_r = tid >> 5, b_c = (tid & 31) * 4;                             \
    float acc[4][4][4] = {};                                                    \
    GEMM128_LOAD(0, 0, APTR, LDA, BPTR, LDB)                                    \
    for (int step = 0; step < 48; step++) {                                     \
        const int s = step & 1;                                                 \
        if (step + 1 < 48) {                                                    \
            GEMM128_LOAD(s ^ 1, (step + 1) * 16, APTR, LDA, BPTR, LDB)          \
            CP_WAIT(1);                                                         \
        } else {                                                                \
            CP_WAIT(0);                                                         \
        }                                                                       \
        __syncthreads();                                                        \
        _Pragma("unroll")                                                       \
        for (int ks = 0; ks < 2; ks++) {                                        \
            const int kk = ks * 8;                                              \
            uint32_t afr[4][4], bfr[4][2];                                      \
            _Pragma("unroll")                                                   \
            for (int mt = 0; mt < 4; mt++) {                                    \
                const int rb = warp_m * 64 + mt * 16;                           \
                afr[mt][0] = __float_as_uint(As[s][rb + g][kk + tg]);           \
                afr[mt][1] = __float_as_uint(As[s][rb + g + 8][kk + tg]);       \
                afr[mt][2] = __float_as_uint(As[s][rb + g][kk + tg + 4]);       \
                afr[mt][3] = __float_as_uint(As[s][rb + g + 8][kk + tg + 4]);   \
            }                                                                   \
            _Pragma("unroll")                                                   \
            for (int nt = 0; nt < 4; nt++) {                                    \
                const int cb = warp_n * 32 + nt * 8;                            \
                bfr[nt][0] = __float_as_uint(Bs[s][kk + tg][cb + g]);           \
                bfr[nt][1] = __float_as_uint(Bs[s][kk + tg + 4][cb + g]);       \
            }                                                                   \
            _Pragma("unroll")                                                   \
            for (int mt = 0; mt < 4; mt++)                                      \
                _Pragma("unroll")                                               \
                for (int nt = 0; nt < 4; nt++)                                  \
                    mma_tf32(acc[mt][nt], afr[mt], bfr[nt]);                    \
        }                                                                       \
        __syncthreads();                                                        \
    }

// ---------------------------------------------------------------------------
// Kernel 1: QKV GEMM (M=8192, N=2304, K=768) on pre-rounded g_x/g_wa.
// Epilogue scatters tf32-rounded q/k/v into [B,H,T,64] with bias.
// ---------------------------------------------------------------------------
__global__ __launch_bounds__(256, 2) void gemm_qkv_tc(const float* __restrict__ bias)
{
    GEMM128_BODY(g_x, 768, g_wa, 2304)

#pragma unroll
    for (int mt = 0; mt < 4; mt++) {
#pragma unroll
        for (int nt = 0; nt < 4; nt++) {
#pragma unroll
            for (int e = 0; e < 4; e++) {
                int m = m0 + warp_m * 64 + mt * 16 + g + (e >> 1) * 8;
                int n = n0 + warp_n * 32 + nt * 8 + 2 * tg + (e & 1);
                float v = to_tf32(acc[mt][nt][e] + bias[n]);
                int bb = m >> 10, t = m & 1023;
                int which = n / 768;
                int c = n - which * 768;
                int hh = c >> 6, d = c & 63;
                float* dst = (which == 0) ? g_q : (which == 1) ? g_k : g_v;
                dst[((((size_t)bb * 12 + hh) << 10) + t) * 64 + d] = v;
            }
        }
    }
}

// ---------------------------------------------------------------------------
// Kernel 3: output projection (M=8192, N=768, K=768) on g_y/g_wp -> d_out.
// Output stays full fp32 (final result).
// ---------------------------------------------------------------------------
__global__ __launch_bounds__(256, 2) void gemm_proj_tc(
    const float* __restrict__ bias, float* __restrict__ out)
{
    GEMM128_BODY(g_y, 768, g_wp, 768)

#pragma unroll
    for (int mt = 0; mt < 4; mt++) {
#pragma unroll
        for (int nt = 0; nt < 4; nt++) {
#pragma unroll
            for (int e = 0; e < 4; e++) {
                int m = m0 + warp_m * 64 + mt * 16 + g + (e >> 1) * 8;
                int n = n0 + warp_n * 32 + nt * 8 + 2 * tg + (e & 1);
                out[(size_t)m * 768 + n] = acc[mt][nt][e] + bias[n];
            }
        }
    }
}

// ---------------------------------------------------------------------------
// Kernel 2: causal flash attention, TF32 tensor cores.  q/k/v arrive
// pre-rounded, so loads are straight copies; P is rounded after exp;
// epilogue writes g_y tf32-rounded (feeds the proj GEMM).
// ---------------------------------------------------------------------------
__global__ __launch_bounds__(256) void attn_tc_kernel()
{
    __shared__ float Qs[64][68];
    __shared__ float Ks[32][68];
    __shared__ float Vs[32][72];
    __shared__ float Ps[64][36];
    __shared__ float s_m[64], s_l[64], s_f[64];

    const int tid = threadIdx.x;
    const int lane = tid & 31;
    const int wid = tid >> 5;
    const int warp_m = wid >> 1, warp_n = wid & 1;
    const int g = lane >> 2, tg = lane & 3;
    const int qi = blockIdx.x, bh = blockIdx.y;
    const int q0 = qi * 64;
    const float* qb = g_q + (size_t)bh * 65536;
    const float* kb = g_k + (size_t)bh * 65536;
    const float* vb = g_v + (size_t)bh * 65536;
    const int mr = warp_m * 16;

#pragma unroll
    for (int r = 0; r < 4; r++) {
        int idx = tid + r * 256;
        int q = idx >> 4, d4 = (idx & 15) * 4;
        *(float4*)&Qs[q][d4] = *(const float4*)(qb + (size_t)(q0 + q) * 64 + d4);
    }
    if (tid < 64) { s_m[tid] = -1e30f; s_l[tid] = 0.0f; }

    float acc_o[4][4] = {};

    const int ktiles = 2 * qi + 2;
    for (int kt = 0; kt < ktiles; kt++) {
        const int k0 = kt * 32;

        float4 kv[2], vv[2];
#pragma unroll
        for (int r = 0; r < 2; r++) {
            int idx = tid + r * 256;
            int kk = idx >> 4, d4 = (idx & 15) * 4;
            kv[r] = *(const float4*)(kb + (size_t)(k0 + kk) * 64 + d4);
            vv[r] = *(const float4*)(vb + (size_t)(k0 + kk) * 64 + d4);
        }
        __syncthreads();
#pragma unroll
        for (int r = 0; r < 2; r++) {
            int idx = tid + r * 256;
            int kk = idx >> 4, d4 = (idx & 15) * 4;
            *(float4*)&Ks[kk][d4] = kv[r];
            *(float4*)&Vs[kk][d4] = vv[r];
        }
        __syncthreads();

        float acc_s[2][4] = {};
#pragma unroll
        for (int ks = 0; ks < 8; ks++) {
            const int kk = ks * 8;
            uint32_t afr[4];
            afr[0] = __float_as_uint(Qs[mr + g][kk + tg]);
            afr[1] = __float_as_uint(Qs[mr + g + 8][kk + tg]);
            afr[2] = __float_as_uint(Qs[mr + g][kk + tg + 4]);
            afr[3] = __float_as_uint(Qs[mr + g + 8][kk + tg + 4]);
#pragma unroll
            for (int nt = 0; nt < 2; nt++) {
                const int nc = warp_n * 16 + nt * 8;
                uint32_t bfr[2];
                bfr[0] = __float_as_uint(Ks[nc + g][kk + tg]);
                bfr[1] = __float_as_uint(Ks[nc + g][kk + tg + 4]);
                mma_tf32(acc_s[nt], afr, bfr);
            }
        }
#pragma unroll
        for (int nt = 0; nt < 2; nt++) {
            const int nc = warp_n * 16 + nt * 8;
#pragma unroll
            for (int e = 0; e < 4; e++) {
                int row = mr + g + (e >> 1) * 8;
                int col = nc + 2 * tg + (e & 1);
                int qg = q0 + row, kg = k0 + col;
                Ps[row][col] = (kg > qg) ? -1e30f : acc_s[nt][e] * 0.125f;
            }
        }
        __syncthreads();

        {
            const int row = tid >> 2, sub = tid & 3;
            float mold = s_m[row];
            float mt = mold;
            float vals[8];
#pragma unroll
            for (int j = 0; j < 8; j++) {
                vals[j] = Ps[row][sub * 8 + j];
                mt = fmaxf(mt, vals[j]);
            }
            mt = fmaxf(mt, __shfl_xor_sync(0xffffffffu, mt, 1));
            mt = fmaxf(mt, __shfl_xor_sync(0xffffffffu, mt, 2));
            float ls = 0.0f;
#pragma unroll
            for (int j = 0; j < 8; j++) {
                float p = __expf(vals[j] - mt);
                Ps[row][sub * 8 + j] = to_tf32(p);
                ls += p;
            }
            ls += __shfl_xor_sync(0xffffffffu, ls, 1);
            ls += __shfl_xor_sync(0xffffffffu, ls, 2);
            if (sub == 0) {
                float f = __expf(mold - mt);
                s_m[row] = mt;
                s_l[row] = s_l[row] * f + ls;
                s_f[row] = f;
            }
        }
        __syncthreads();

        float f0 = s_f[mr + g], f1 = s_f[mr + g + 8];
#pragma unroll
        for (int nt = 0; nt < 4; nt++) {
            acc_o[nt][0] *= f0; acc_o[nt][1] *= f0;
            acc_o[nt][2] *= f1; acc_o[nt][3] *= f1;
        }
#pragma unroll
        for (int ks = 0; ks < 4; ks++) {
            const int kk = ks * 8;
            uint32_t afr[4];
            afr[0] = __float_as_uint(Ps[mr + g][kk + tg]);
            afr[1] = __float_as_uint(Ps[mr + g + 8][kk + tg]);
            afr[2] = __float_as_uint(Ps[mr + g][kk + tg + 4]);
            afr[3] = __float_as_uint(Ps[mr + g + 8][kk + tg + 4]);
#pragma unroll
            for (int nt = 0; nt < 4; nt++) {
                const int nc = warp_n * 32 + nt * 8;
                uint32_t bfr[2];
                bfr[0] = __float_as_uint(Vs[kk + tg][nc + g]);
                bfr[1] = __float_as_uint(Vs[kk + tg + 4][nc + g]);
                mma_tf32(acc_o[nt], afr, bfr);
            }
        }
    }

    const int b = bh / 12, h = bh - b * 12;
    float inv0 = 1.0f / s_l[mr + g];
    float inv1 = 1.0f / s_l[mr + g + 8];
    const int t0 = q0 + mr + g, t1 = t0 + 8;
#pragma unroll
    for (int nt = 0; nt < 4; nt++) {
        int col = warp_n * 32 + nt * 8 + 2 * tg;
        float* d0 = g_y + ((size_t)(b * 1024 + t0)) * 768 + h * 64 + col;
        float* d1 = g_y + ((size_t)(b * 1024 + t1)) * 768 + h * 64 + col;
        *(float2*)d0 = make_float2(to_tf32(acc_o[nt][0] * inv0),
                                   to_tf32(acc_o[nt][1] * inv0));
        *(float2*)d1 = make_float2(to_tf32(acc_o[nt][2] * inv1),
                                   to_tf32(acc_o[nt][3] * inv1));
    }
}

// ---------------------------------------------------------------------------
extern "C" void kernel_launch(void* const* d_in, const int* in_sizes, int n_in,
                              void* d_out, int out_size)
{
    const float* x      = (const float*)d_in[0];
    const float* w_attn = (const float*)d_in[1];
    const float* b_attn = (const float*)d_in[2];
    const float* w_proj = (const float*)d_in[3];
    const float* b_proj = (const float*)d_in[4];
    float* out = (float*)d_out;

    preround_kernel<<<8448, 256>>>(x, w_attn, w_proj);
    gemm_qkv_tc<<<dim3(18, 64), 256>>>(b_attn);
    attn_tc_kernel<<<dim3(16, 96), 256>>>();
    gemm_proj_tc<<<dim3(6, 64), 256>>>(b_proj, out);
}

// round 8
// speedup vs baseline: 1.5238x; 1.0109x over previous
#include <cuda_runtime.h>
#include <cuda_bf16.h>
#include <cstdint>

// Problem constants: B=8, T=1024, C=768, H=12, HD=64
__device__ float g_q[6291456];
__device__ float g_k[6291456];
__device__ float g_v[6291456];
__device__ float g_y[6291456];
// Pre-rounded (tf32) copies of inputs
__device__ float g_x[6291456];
__device__ float g_wa[1769472];   // 768*2304
__device__ float g_wp[589824];    // 768*768

// ---------------------------------------------------------------------------
// helpers
// ---------------------------------------------------------------------------
__device__ __forceinline__ float to_tf32(float x) {
    uint32_t u;
    asm("cvt.rna.tf32.f32 %0, %1;" : "=r"(u) : "f"(x));
    return __uint_as_float(u);
}
__device__ __forceinline__ void mma_tf32(float* c, const uint32_t* a, const uint32_t* b) {
    asm volatile(
        "mma.sync.aligned.m16n8k8.row.col.f32.tf32.tf32.f32 "
        "{%0,%1,%2,%3},{%4,%5,%6,%7},{%8,%9},{%0,%1,%2,%3};"
        : "+f"(c[0]), "+f"(c[1]), "+f"(c[2]), "+f"(c[3])
        : "r"(a[0]), "r"(a[1]), "r"(a[2]), "r"(a[3]), "r"(b[0]), "r"(b[1]));
}
__device__ __forceinline__ uint32_t smem_u32(const void* p) {
    return (uint32_t)__cvta_generic_to_shared(p);
}
#define CP_ASYNC16(dst, src) \
    asm volatile("cp.async.cg.shared.global [%0], [%1], 16;\n" :: "r"(dst), "l"(src))
#define CP_COMMIT() asm volatile("cp.async.commit_group;\n")
#define CP_WAIT(N)  asm volatile("cp.async.wait_group %0;\n" :: "n"(N))

// ---------------------------------------------------------------------------
// Kernel 0: pre-round x, w_attn, w_proj to tf32.
// ---------------------------------------------------------------------------
__global__ __launch_bounds__(256) void preround_kernel(
    const float* __restrict__ x, const float* __restrict__ wa,
    const float* __restrict__ wp)
{
    long i = (long)blockIdx.x * 256 + threadIdx.x;
    const float4* src;
    float4* dst;
    if (i < 1572864)      { src = (const float4*)x  + i;            dst = (float4*)g_x  + i; }
    else if (i < 2015232) { src = (const float4*)wa + (i - 1572864); dst = (float4*)g_wa + (i - 1572864); }
    else                  { src = (const float4*)wp + (i - 2015232); dst = (float4*)g_wp + (i - 2015232); }
    float4 v = *src;
    v.x = to_tf32(v.x); v.y = to_tf32(v.y);
    v.z = to_tf32(v.z); v.w = to_tf32(v.w);
    *dst = v;
}

// ---------------------------------------------------------------------------
// TF32 GEMM v4: block tile 128x128, 8 warps (2m x 4n), warp tile 64x32,
// K-step 16, 3-STAGE cp.async pipeline, ONE __syncthreads per step.
// Dynamic smem: As[3][128][20] + Bs[3][16][136] = 56832 bytes.
//   As pitch 20  -> A-frag banks (20g+tg)%32 bijective, conflict-free
//   Bs pitch 136 -> B-frag banks (8tg+g)%32 bijective, conflict-free
// ---------------------------------------------------------------------------
#define GEMM_SMEM_BYTES 56832

#define GEMM128_LOAD(S, K0, APTR, LDA, BPTR, LDB)                               \
    _Pragma("unroll")                                                           \
    for (int i = 0; i < 2; i++) {                                               \
        int r = a_r + i * 64;                                                   \
        CP_ASYNC16(smem_u32(&As[S][r][a_c]),                                    \
                   (APTR) + (size_t)(m0 + r) * (LDA) + (K0) + a_c);             \
    }                                                                           \
    _Pragma("unroll")                                                           \
    for (int i = 0; i < 2; i++) {                                               \
        int r = b_r + i * 8;                                                    \
        CP_ASYNC16(smem_u32(&Bs[S][r][b_c]),                                    \
                   (BPTR) + (size_t)((K0) + r) * (LDB) + n0 + b_c);             \
    }                                                                           \
    CP_COMMIT();

#define GEMM128_BODY(APTR, LDA, BPTR, LDB)                                      \
    extern __shared__ char smem_raw[];                                          \
    float (*As)[128][20] = (float (*)[128][20])smem_raw;                        \
    float (*Bs)[16][136] = (float (*)[16][136])(smem_raw + 3 * 128 * 20 * 4);   \
    const int tid  = threadIdx.x;                                               \
    const int lane = tid & 31;                                                  \
    const int wid  = tid >> 5;                                                  \
    const int warp_m = wid & 1, warp_n = wid >> 1;                              \
    const int g = lane >> 2, tg = lane & 3;                                     \
    const int m0 = blockIdx.y * 128, n0 = blockIdx.x * 128;                     \
    const int a_r = tid >> 2, a_c = (tid & 3) * 4;                              \
    const int b_r = tid >> 5, b_c = (tid & 31) * 4;                             \
    float acc[4][4][4] = {};                                                    \
    GEMM128_LOAD(0, 0, APTR, LDA, BPTR, LDB)                                    \
    GEMM128_LOAD(1, 16, APTR, LDA, BPTR, LDB)                                   \
    int sidx = 0, pidx = 2;                                                     \
    for (int step = 0; step < 48; step++) {                                     \
        if (step < 47) { CP_WAIT(1); } else { CP_WAIT(0); }                     \
        __syncthreads();                                                        \
        if (step + 2 < 48) {                                                    \
            GEMM128_LOAD(pidx, (step + 2) * 16, APTR, LDA, BPTR, LDB)           \
        }                                                                       \
        const int s = sidx;                                                     \
        _Pragma("unroll")                                                       \
        for (int ks = 0; ks < 2; ks++) {                                        \
            const int kk = ks * 8;                                              \
            uint32_t afr[4][4], bfr[4][2];                                      \
            _Pragma("unroll")                                                   \
            for (int mt = 0; mt < 4; mt++) {                                    \
                const int rb = warp_m * 64 + mt * 16;                           \
                afr[mt][0] = __float_as_uint(As[s][rb + g][kk + tg]);           \
                afr[mt][1] = __float_as_uint(As[s][rb + g + 8][kk + tg]);       \
                afr[mt][2] = __float_as_uint(As[s][rb + g][kk + tg + 4]);       \
                afr[mt][3] = __float_as_uint(As[s][rb + g + 8][kk + tg + 4]);   \
            }                                                                   \
            _Pragma("unroll")                                                   \
            for (int nt = 0; nt < 4; nt++) {                                    \
                const int cb = warp_n * 32 + nt * 8;                            \
                bfr[nt][0] = __float_as_uint(Bs[s][kk + tg][cb + g]);           \
                bfr[nt][1] = __float_as_uint(Bs[s][kk + tg + 4][cb + g]);       \
            }                                                                   \
            _Pragma("unroll")                                                   \
            for (int mt = 0; mt < 4; mt++)                                      \
                _Pragma("unroll")                                               \
                for (int nt = 0; nt < 4; nt++)                                  \
                    mma_tf32(acc[mt][nt], afr[mt], bfr[nt]);                    \
        }                                                                       \
        sidx = (sidx == 2) ? 0 : sidx + 1;                                      \
        pidx = (pidx == 2) ? 0 : pidx + 1;                                      \
    }

// ---------------------------------------------------------------------------
// Kernel 1: QKV GEMM (M=8192, N=2304, K=768) on pre-rounded g_x/g_wa.
// ---------------------------------------------------------------------------
__global__ __launch_bounds__(256, 2) void gemm_qkv_tc(const float* __restrict__ bias)
{
    GEMM128_BODY(g_x, 768, g_wa, 2304)

#pragma unroll
    for (int mt = 0; mt < 4; mt++) {
#pragma unroll
        for (int nt = 0; nt < 4; nt++) {
#pragma unroll
            for (int e = 0; e < 4; e++) {
                int m = m0 + warp_m * 64 + mt * 16 + g + (e >> 1) * 8;
                int n = n0 + warp_n * 32 + nt * 8 + 2 * tg + (e & 1);
                float v = to_tf32(acc[mt][nt][e] + bias[n]);
                int bb = m >> 10, t = m & 1023;
                int which = n / 768;
                int c = n - which * 768;
                int hh = c >> 6, d = c & 63;
                float* dst = (which == 0) ? g_q : (which == 1) ? g_k : g_v;
                dst[((((size_t)bb * 12 + hh) << 10) + t) * 64 + d] = v;
            }
        }
    }
}

// ---------------------------------------------------------------------------
// Kernel 3: output projection (M=8192, N=768, K=768) on g_y/g_wp -> d_out.
// ---------------------------------------------------------------------------
__global__ __launch_bounds__(256, 2) void gemm_proj_tc(
    const float* __restrict__ bias, float* __restrict__ out)
{
    GEMM128_BODY(g_y, 768, g_wp, 768)

#pragma unroll
    for (int mt = 0; mt < 4; mt++) {
#pragma unroll
        for (int nt = 0; nt < 4; nt++) {
#pragma unroll
            for (int e = 0; e < 4; e++) {
                int m = m0 + warp_m * 64 + mt * 16 + g + (e >> 1) * 8;
                int n = n0 + warp_n * 32 + nt * 8 + 2 * tg + (e & 1);
                out[(size_t)m * 768 + n] = acc[mt][nt][e] + bias[n];
            }
        }
    }
}

// ---------------------------------------------------------------------------
// Kernel 2: causal flash attention, TF32 tensor cores (unchanged from R7).
// ---------------------------------------------------------------------------
__global__ __launch_bounds__(256) void attn_tc_kernel()
{
    __shared__ float Qs[64][68];
    __shared__ float Ks[32][68];
    __shared__ float Vs[32][72];
    __shared__ float Ps[64][36];
    __shared__ float s_m[64], s_l[64], s_f[64];

    const int tid = threadIdx.x;
    const int lane = tid & 31;
    const int wid = tid >> 5;
    const int warp_m = wid >> 1, warp_n = wid & 1;
    const int g = lane >> 2, tg = lane & 3;
    const int qi = blockIdx.x, bh = blockIdx.y;
    const int q0 = qi * 64;
    const float* qb = g_q + (size_t)bh * 65536;
    const float* kb = g_k + (size_t)bh * 65536;
    const float* vb = g_v + (size_t)bh * 65536;
    const int mr = warp_m * 16;

#pragma unroll
    for (int r = 0; r < 4; r++) {
        int idx = tid + r * 256;
        int q = idx >> 4, d4 = (idx & 15) * 4;
        *(float4*)&Qs[q][d4] = *(const float4*)(qb + (size_t)(q0 + q) * 64 + d4);
    }
    if (tid < 64) { s_m[tid] = -1e30f; s_l[tid] = 0.0f; }

    float acc_o[4][4] = {};

    const int ktiles = 2 * qi + 2;
    for (int kt = 0; kt < ktiles; kt++) {
        const int k0 = kt * 32;

        float4 kv[2], vv[2];
#pragma unroll
        for (int r = 0; r < 2; r++) {
            int idx = tid + r * 256;
            int kk = idx >> 4, d4 = (idx & 15) * 4;
            kv[r] = *(const float4*)(kb + (size_t)(k0 + kk) * 64 + d4);
            vv[r] = *(const float4*)(vb + (size_t)(k0 + kk) * 64 + d4);
        }
        __syncthreads();
#pragma unroll
        for (int r = 0; r < 2; r++) {
            int idx = tid + r * 256;
            int kk = idx >> 4, d4 = (idx & 15) * 4;
            *(float4*)&Ks[kk][d4] = kv[r];
            *(float4*)&Vs[kk][d4] = vv[r];
        }
        __syncthreads();

        float acc_s[2][4] = {};
#pragma unroll
        for (int ks = 0; ks < 8; ks++) {
            const int kk = ks * 8;
            uint32_t afr[4];
            afr[0] = __float_as_uint(Qs[mr + g][kk + tg]);
            afr[1] = __float_as_uint(Qs[mr + g + 8][kk + tg]);
            afr[2] = __float_as_uint(Qs[mr + g][kk + tg + 4]);
            afr[3] = __float_as_uint(Qs[mr + g + 8][kk + tg + 4]);
#pragma unroll
            for (int nt = 0; nt < 2; nt++) {
                const int nc = warp_n * 16 + nt * 8;
                uint32_t bfr[2];
                bfr[0] = __float_as_uint(Ks[nc + g][kk + tg]);
                bfr[1] = __float_as_uint(Ks[nc + g][kk + tg + 4]);
                mma_tf32(acc_s[nt], afr, bfr);
            }
        }
#pragma unroll
        for (int nt = 0; nt < 2; nt++) {
            const int nc = warp_n * 16 + nt * 8;
#pragma unroll
            for (int e = 0; e < 4; e++) {
                int row = mr + g + (e >> 1) * 8;
                int col = nc + 2 * tg + (e & 1);
                int qg = q0 + row, kg = k0 + col;
                Ps[row][col] = (kg > qg) ? -1e30f : acc_s[nt][e] * 0.125f;
            }
        }
        __syncthreads();

        {
            const int row = tid >> 2, sub = tid & 3;
            float mold = s_m[row];
            float mt = mold;
            float vals[8];
#pragma unroll
            for (int j = 0; j < 8; j++) {
                vals[j] = Ps[row][sub * 8 + j];
                mt = fmaxf(mt, vals[j]);
            }
            mt = fmaxf(mt, __shfl_xor_sync(0xffffffffu, mt, 1));
            mt = fmaxf(mt, __shfl_xor_sync(0xffffffffu, mt, 2));
            float ls = 0.0f;
#pragma unroll
            for (int j = 0; j < 8; j++) {
                float p = __expf(vals[j] - mt);
                Ps[row][sub * 8 + j] = to_tf32(p);
                ls += p;
            }
            ls += __shfl_xor_sync(0xffffffffu, ls, 1);
            ls += __shfl_xor_sync(0xffffffffu, ls, 2);
            if (sub == 0) {
                float f = __expf(mold - mt);
                s_m[row] = mt;
                s_l[row] = s_l[row] * f + ls;
                s_f[row] = f;
            }
        }
        __syncthreads();

        float f0 = s_f[mr + g], f1 = s_f[mr + g + 8];
#pragma unroll
        for (int nt = 0; nt < 4; nt++) {
            acc_o[nt][0] *= f0; acc_o[nt][1] *= f0;
            acc_o[nt][2] *= f1; acc_o[nt][3] *= f1;
        }
#pragma unroll
        for (int ks = 0; ks < 4; ks++) {
            const int kk = ks * 8;
            uint32_t afr[4];
            afr[0] = __float_as_uint(Ps[mr + g][kk + tg]);
            afr[1] = __float_as_uint(Ps[mr + g + 8][kk + tg]);
            afr[2] = __float_as_uint(Ps[mr + g][kk + tg + 4]);
            afr[3] = __float_as_uint(Ps[mr + g + 8][kk + tg + 4]);
#pragma unroll
            for (int nt = 0; nt < 4; nt++) {
                const int nc = warp_n * 32 + nt * 8;
                uint32_t bfr[2];
                bfr[0] = __float_as_uint(Vs[kk + tg][nc + g]);
                bfr[1] = __float_as_uint(Vs[kk + tg + 4][nc + g]);
                mma_tf32(acc_o[nt], afr, bfr);
            }
        }
    }

    const int b = bh / 12, h = bh - b * 12;
    float inv0 = 1.0f / s_l[mr + g];
    float inv1 = 1.0f / s_l[mr + g + 8];
    const int t0 = q0 + mr + g, t1 = t0 + 8;
#pragma unroll
    for (int nt = 0; nt < 4; nt++) {
        int col = warp_n * 32 + nt * 8 + 2 * tg;
        float* d0 = g_y + ((size_t)(b * 1024 + t0)) * 768 + h * 64 + col;
        float* d1 = g_y + ((size_t)(b * 1024 + t1)) * 768 + h * 64 + col;
        *(float2*)d0 = make_float2(to_tf32(acc_o[nt][0] * inv0),
                                   to_tf32(acc_o[nt][1] * inv0));
        *(float2*)d1 = make_float2(to_tf32(acc_o[nt][2] * inv1),
                                   to_tf32(acc_o[nt][3] * inv1));
    }
}

// ---------------------------------------------------------------------------
extern "C" void kernel_launch(void* const* d_in, const int* in_sizes, int n_in,
                              void* d_out, int out_size)
{
    const float* x      = (const float*)d_in[0];
    const float* w_attn = (const float*)d_in[1];
    const float* b_attn = (const float*)d_in[2];
    const float* w_proj = (const float*)d_in[3];
    const float* b_proj = (const float*)d_in[4];
    float* out = (float*)d_out;

    static bool attr_set = false;
    if (!attr_set) {
        cudaFuncSetAttribute(gemm_qkv_tc,
            cudaFuncAttributeMaxDynamicSharedMemorySize, GEMM_SMEM_BYTES);
        cudaFuncSetAttribute(gemm_proj_tc,
            cudaFuncAttributeMaxDynamicSharedMemorySize, GEMM_SMEM_BYTES);
        attr_set = true;
    }

    preround_kernel<<<8448, 256>>>(x, w_attn, w_proj);
    gemm_qkv_tc<<<dim3(18, 64), 256, GEMM_SMEM_BYTES>>>(b_attn);
    attn_tc_kernel<<<dim3(16, 96), 256>>>();
    gemm_proj_tc<<<dim3(6, 64), 256, GEMM_SMEM_BYTES>>>(b_proj, out);
}

// round 10
// speedup vs baseline: 1.5857x; 1.0406x over previous
#include <cuda_runtime.h>
#include <cuda_bf16.h>
#include <cstdint>

// Problem constants: B=8, T=1024, C=768, H=12, HD=64
__device__ float g_q[6291456];
__device__ float g_k[6291456];
__device__ float g_v[6291456];
__device__ float g_y[6291456];
// Pre-rounded (tf32) copies of inputs
__device__ float g_x[6291456];
__device__ float g_wa[1769472];   // 768*2304
__device__ float g_wp[589824];    // 768*768

// ---------------------------------------------------------------------------
// helpers
// ---------------------------------------------------------------------------
__device__ __forceinline__ float to_tf32(float x) {
    uint32_t u;
    asm("cvt.rna.tf32.f32 %0, %1;" : "=r"(u) : "f"(x));
    return __uint_as_float(u);
}
__device__ __forceinline__ void mma_tf32(float* c, const uint32_t* a, const uint32_t* b) {
    asm volatile(
        "mma.sync.aligned.m16n8k8.row.col.f32.tf32.tf32.f32 "
        "{%0,%1,%2,%3},{%4,%5,%6,%7},{%8,%9},{%0,%1,%2,%3};"
        : "+f"(c[0]), "+f"(c[1]), "+f"(c[2]), "+f"(c[3])
        : "r"(a[0]), "r"(a[1]), "r"(a[2]), "r"(a[3]), "r"(b[0]), "r"(b[1]));
}
__device__ __forceinline__ uint32_t smem_u32(const void* p) {
    return (uint32_t)__cvta_generic_to_shared(p);
}
#define CP_ASYNC16(dst, src) \
    asm volatile("cp.async.cg.shared.global [%0], [%1], 16;\n" :: "r"(dst), "l"(src))
#define CP_COMMIT() asm volatile("cp.async.commit_group;\n")
#define CP_WAIT(N)  asm volatile("cp.async.wait_group %0;\n" :: "n"(N))

// ---------------------------------------------------------------------------
// Kernel 0: pre-round x, w_attn, w_proj to tf32.
// ---------------------------------------------------------------------------
__global__ __launch_bounds__(256) void preround_kernel(
    const float* __restrict__ x, const float* __restrict__ wa,
    const float* __restrict__ wp)
{
    long i = (long)blockIdx.x * 256 + threadIdx.x;
    const float4* src;
    float4* dst;
    if (i < 1572864)      { src = (const float4*)x  + i;            dst = (float4*)g_x  + i; }
    else if (i < 2015232) { src = (const float4*)wa + (i - 1572864); dst = (float4*)g_wa + (i - 1572864); }
    else                  { src = (const float4*)wp + (i - 2015232); dst = (float4*)g_wp + (i - 2015232); }
    float4 v = *src;
    v.x = to_tf32(v.x); v.y = to_tf32(v.y);
    v.z = to_tf32(v.z); v.w = to_tf32(v.w);
    *dst = v;
}

// ---------------------------------------------------------------------------
// TF32 GEMM (R8, unchanged): block tile 128x128, 8 warps (2m x 4n),
// warp tile 64x32, K-step 16, 3-stage cp.async, one __syncthreads per step.
// Dynamic smem: As[3][128][20] + Bs[3][16][136] = 56832 bytes.
// ---------------------------------------------------------------------------
#define GEMM_SMEM_BYTES 56832

#define GEMM128_LOAD(S, K0, APTR, LDA, BPTR, LDB)                               \
    _Pragma("unroll")                                                           \
    for (int i = 0; i < 2; i++) {                                               \
        int r = a_r + i * 64;                                                   \
        CP_ASYNC16(smem_u32(&As[S][r][a_c]),                                    \
                   (APTR) + (size_t)(m0 + r) * (LDA) + (K0) + a_c);             \
    }                                                                           \
    _Pragma("unroll")                                                           \
    for (int i = 0; i < 2; i++) {                                               \
        int r = b_r + i * 8;                                                    \
        CP_ASYNC16(smem_u32(&Bs[S][r][b_c]),                                    \
                   (BPTR) + (size_t)((K0) + r) * (LDB) + n0 + b_c);             \
    }                                                                           \
    CP_COMMIT();

#define GEMM128_BODY(APTR, LDA, BPTR, LDB)                                      \
    extern __shared__ char smem_raw[];                                          \
    float (*As)[128][20] = (float (*)[128][20])smem_raw;                        \
    float (*Bs)[16][136] = (float (*)[16][136])(smem_raw + 3 * 128 * 20 * 4);   \
    const int tid  = threadIdx.x;                                               \
    const int lane = tid & 31;                                                  \
    const int wid  = tid >> 5;                                                  \
    const int warp_m = wid & 1, warp_n = wid >> 1;                              \
    const int g = lane >> 2, tg = lane & 3;                                     \
    const int m0 = blockIdx.y * 128, n0 = blockIdx.x * 128;                     \
    const int a_r = tid >> 2, a_c = (tid & 3) * 4;                              \
    const int b_r = tid >> 5, b_c = (tid & 31) * 4;                             \
    float acc[4][4][4] = {};                                                    \
    GEMM128_LOAD(0, 0, APTR, LDA, BPTR, LDB)                                    \
    GEMM128_LOAD(1, 16, APTR, LDA, BPTR, LDB)                                   \
    int sidx = 0, pidx = 2;                                                     \
    for (int step = 0; step < 48; step++) {                                     \
        if (step < 47) { CP_WAIT(1); } else { CP_WAIT(0); }                     \
        __syncthreads();                                                        \
        if (step + 2 < 48) {                                                    \
            GEMM128_LOAD(pidx, (step + 2) * 16, APTR, LDA, BPTR, LDB)           \
        }                                                                       \
        const int s = sidx;                                                     \
        _Pragma("unroll")                                                       \
        for (int ks = 0; ks < 2; ks++) {                                        \
            const int kk = ks * 8;                                              \
            uint32_t afr[4][4], bfr[4][2];                                      \
            _Pragma("unroll")                                                   \
            for (int mt = 0; mt < 4; mt++) {                                    \
                const int rb = warp_m * 64 + mt * 16;                           \
                afr[mt][0] = __float_as_uint(As[s][rb + g][kk + tg]);           \
                afr[mt][1] = __float_as_uint(As[s][rb + g + 8][kk + tg]);       \
                afr[mt][2] = __float_as_uint(As[s][rb + g][kk + tg + 4]);       \
                afr[mt][3] = __float_as_uint(As[s][rb + g + 8][kk + tg + 4]);   \
            }                                                                   \
            _Pragma("unroll")                                                   \
            for (int nt = 0; nt < 4; nt++) {                                    \
                const int cb = warp_n * 32 + nt * 8;                            \
                bfr[nt][0] = __float_as_uint(Bs[s][kk + tg][cb + g]);           \
                bfr[nt][1] = __float_as_uint(Bs[s][kk + tg + 4][cb + g]);       \
            }                                                                   \
            _Pragma("unroll")                                                   \
            for (int mt = 0; mt < 4; mt++)                                      \
                _Pragma("unroll")                                               \
                for (int nt = 0; nt < 4; nt++)                                  \
                    mma_tf32(acc[mt][nt], afr[mt], bfr[nt]);                    \
        }                                                                       \
        sidx = (sidx == 2) ? 0 : sidx + 1;                                      \
        pidx = (pidx == 2) ? 0 : pidx + 1;                                      \
    }

// ---------------------------------------------------------------------------
// Kernel 1: QKV GEMM (M=8192, N=2304, K=768).
// ---------------------------------------------------------------------------
__global__ __launch_bounds__(256, 2) void gemm_qkv_tc(const float* __restrict__ bias)
{
    GEMM128_BODY(g_x, 768, g_wa, 2304)

#pragma unroll
    for (int mt = 0; mt < 4; mt++) {
#pragma unroll
        for (int nt = 0; nt < 4; nt++) {
#pragma unroll
            for (int e = 0; e < 4; e++) {
                int m = m0 + warp_m * 64 + mt * 16 + g + (e >> 1) * 8;
                int n = n0 + warp_n * 32 + nt * 8 + 2 * tg + (e & 1);
                float v = to_tf32(acc[mt][nt][e] + bias[n]);
                int bb = m >> 10, t = m & 1023;
                int which = n / 768;
                int c = n - which * 768;
                int hh = c >> 6, d = c & 63;
                float* dst = (which == 0) ? g_q : (which == 1) ? g_k : g_v;
                dst[((((size_t)bb * 12 + hh) << 10) + t) * 64 + d] = v;
            }
        }
    }
}

// ---------------------------------------------------------------------------
// Kernel 3: output projection (M=8192, N=768, K=768) -> d_out.
// ---------------------------------------------------------------------------
__global__ __launch_bounds__(256, 2) void gemm_proj_tc(
    const float* __restrict__ bias, float* __restrict__ out)
{
    GEMM128_BODY(g_y, 768, g_wp, 768)

#pragma unroll
    for (int mt = 0; mt < 4; mt++) {
#pragma unroll
        for (int nt = 0; nt < 4; nt++) {
#pragma unroll
            for (int e = 0; e < 4; e++) {
                int m = m0 + warp_m * 64 + mt * 16 + g + (e >> 1) * 8;
                int n = n0 + warp_n * 32 + nt * 8 + 2 * tg + (e & 1);
                out[(size_t)m * 768 + n] = acc[mt][nt][e] + bias[n];
            }
        }
    }
}

// ---------------------------------------------------------------------------
// Kernel 2 v2: causal flash attention, TF32 mma.sync.
//   Q tile 64 (registers), K/V tile 64, 8 warps (4m x 2n).
//   Dynamic smem 54016B: Ps[64][68] (aliases Q staging) | Ks[64][68] |
//   Vs[64][72] | s_m/s_l/s_f[64].  2 CTAs/SM.
//   Frag bank maps: Ps/Ks pitch 68 -> (4g+tg)%32; Vs pitch 72 -> (8tg+g)%32.
// ---------------------------------------------------------------------------
#define ATTN_SMEM_BYTES 54016

__global__ __launch_bounds__(256, 2) void attn_tc_kernel()
{
    extern __shared__ char smem_raw[];
    float (*Ps)[68] = (float (*)[68])smem_raw;            // also Q staging
    float (*Ks)[68] = (float (*)[68])(smem_raw + 17408);
    float (*Vs)[72] = (float (*)[72])(smem_raw + 34816);
    float* s_m = (float*)(smem_raw + 53248);
    float* s_l = s_m + 64;
    float* s_f = s_m + 128;

    const int tid = threadIdx.x;
    const int lane = tid & 31;
    const int wid = tid >> 5;
    const int warp_m = wid & 3, warp_n = wid >> 2;
    const int g = lane >> 2, tg = lane & 3;
    const int qi = blockIdx.x, bh = blockIdx.y;
    const int q0 = qi * 64;
    const float* qb = g_q + (size_t)bh * 65536;
    const float* kb = g_k + (size_t)bh * 65536;
    const float* vb = g_v + (size_t)bh * 65536;
    const int mr = warp_m * 16;

    // Stage Q through smem (coalesced), then hoist this warp's A-fragments
    // into registers for the whole kernel.
#pragma unroll
    for (int r = 0; r < 4; r++) {
        int idx = tid + r * 256;
        int q = idx >> 4, d4 = (idx & 15) * 4;
        *(float4*)&Ps[q][d4] = *(const float4*)(qb + (size_t)(q0 + q) * 64 + d4);
    }
    if (tid < 64) { s_m[tid] = -1e30f; s_l[tid] = 0.0f; }
    __syncthreads();

    uint32_t qfr[8][4];
#pragma unroll
    for (int ks = 0; ks < 8; ks++) {
        const int kk = ks * 8;
        qfr[ks][0] = __float_as_uint(Ps[mr + g][kk + tg]);
        qfr[ks][1] = __float_as_uint(Ps[mr + g + 8][kk + tg]);
        qfr[ks][2] = __float_as_uint(Ps[mr + g][kk + tg + 4]);
        qfr[ks][3] = __float_as_uint(Ps[mr + g + 8][kk + tg + 4]);
    }

    float acc_o[4][4] = {};

    const int ktiles = qi + 1;
    for (int kt = 0; kt < ktiles; kt++) {
        const int k0 = kt * 64;
        const bool diag = (kt == qi);

        __syncthreads();   // prior iter's Ps/Ks/Vs reads done; qfr loads done
#pragma unroll
        for (int r = 0; r < 4; r++) {
            int idx = tid + r * 256;
            int kk = idx >> 4, d4 = (idx & 15) * 4;
            float4 kv = *(const float4*)(kb + (size_t)(k0 + kk) * 64 + d4);
            float4 vv = *(const float4*)(vb + (size_t)(k0 + kk) * 64 + d4);
            *(float4*)&Ks[kk][d4] = kv;
            *(float4*)&Vs[kk][d4] = vv;
        }
        __syncthreads();

        // ---- S = Q K^T (warp tile 16x32, k-cols warp_n*32..+32) ----
        float acc_s[4][4] = {};
#pragma unroll
        for (int ks = 0; ks < 8; ks++) {
            const int kk = ks * 8;
#pragma unroll
            for (int nt = 0; nt < 4; nt++) {
                const int nc = warp_n * 32 + nt * 8;
                uint32_t bfr[2];
                bfr[0] = __float_as_uint(Ks[nc + g][kk + tg]);
                bfr[1] = __float_as_uint(Ks[nc + g][kk + tg + 4]);
                mma_tf32(acc_s[nt], qfr[ks], bfr);
            }
        }
        // mask (diagonal tile only) + scale -> Ps
#pragma unroll
        for (int nt = 0; nt < 4; nt++) {
            const int nc = warp_n * 32 + nt * 8;
#pragma unroll
            for (int e = 0; e < 4; e++) {
                int row = mr + g + (e >> 1) * 8;
                int col = nc + 2 * tg + (e & 1);
                float v = acc_s[nt][e] * 0.125f;
                if (diag && col > row) v = -1e30f;
                Ps[row][col] = v;
            }
        }
        __syncthreads();

        // ---- online softmax: 4 threads per row, 16 cols each ----
        {
            const int row = tid >> 2, sub = tid & 3;
            float mold = s_m[row];
            float mt = mold;
            float vals[16];
#pragma unroll
            for (int j = 0; j < 16; j++) {
                vals[j] = Ps[row][sub * 16 + j];
                mt = fmaxf(mt, vals[j]);
            }
            mt = fmaxf(mt, __shfl_xor_sync(0xffffffffu, mt, 1));
            mt = fmaxf(mt, __shfl_xor_sync(0xffffffffu, mt, 2));
            float ls = 0.0f;
#pragma unroll
            for (int j = 0; j < 16; j++) {
                float p = __expf(vals[j] - mt);
                Ps[row][sub * 16 + j] = to_tf32(p);
                ls += p;
            }
            ls += __shfl_xor_sync(0xffffffffu, ls, 1);
            ls += __shfl_xor_sync(0xffffffffu, ls, 2);
            if (sub == 0) {
                float f = __expf(mold - mt);
                s_m[row] = mt;
                s_l[row] = s_l[row] * f + ls;
                s_f[row] = f;
            }
        }
        __syncthreads();

        // ---- rescale O, accumulate P @ V (warp tile 16x32 over d) ----
        float f0 = s_f[mr + g], f1 = s_f[mr + g + 8];
#pragma unroll
        for (int nt = 0; nt < 4; nt++) {
            acc_o[nt][0] *= f0; acc_o[nt][1] *= f0;
            acc_o[nt][2] *= f1; acc_o[nt][3] *= f1;
        }
#pragma unroll
        for (int ks = 0; ks < 8; ks++) {
            const int kk = ks * 8;
            uint32_t afr[4];
            afr[0] = __float_as_uint(Ps[mr + g][kk + tg]);
            afr[1] = __float_as_uint(Ps[mr + g + 8][kk + tg]);
            afr[2] = __float_as_uint(Ps[mr + g][kk + tg + 4]);
            afr[3] = __float_as_uint(Ps[mr + g + 8][kk + tg + 4]);
#pragma unroll
            for (int nt = 0; nt < 4; nt++) {
                const int nc = warp_n * 32 + nt * 8;
                uint32_t bfr[2];
                bfr[0] = __float_as_uint(Vs[kk + tg][nc + g]);
                bfr[1] = __float_as_uint(Vs[kk + tg + 4][nc + g]);
                mma_tf32(acc_o[nt], afr, bfr);
            }
        }
    }

    // ---- epilogue: normalize, write g_y in [B,T,C] layout (tf32) ----
    const int b = bh / 12, h = bh - b * 12;
    float inv0 = 1.0f / s_l[mr + g];
    float inv1 = 1.0f / s_l[mr + g + 8];
    const int t0 = q0 + mr + g, t1 = t0 + 8;
#pragma unroll
    for (int nt = 0; nt < 4; nt++) {
        int col = warp_n * 32 + nt * 8 + 2 * tg;
        float* d0 = g_y + ((size_t)(b * 1024 + t0)) * 768 + h * 64 + col;
        float* d1 = g_y + ((size_t)(b * 1024 + t1)) * 768 + h * 64 + col;
        *(float2*)d0 = make_float2(to_tf32(acc_o[nt][0] * inv0),
                                   to_tf32(acc_o[nt][1] * inv0));
        *(float2*)d1 = make_float2(to_tf32(acc_o[nt][2] * inv1),
                                   to_tf32(acc_o[nt][3] * inv1));
    }
}

// ---------------------------------------------------------------------------
extern "C" void kernel_launch(void* const* d_in, const int* in_sizes, int n_in,
                              void* d_out, int out_size)
{
    const float* x      = (const float*)d_in[0];
    const float* w_attn = (const float*)d_in[1];
    const float* b_attn = (const float*)d_in[2];
    const float* w_proj = (const float*)d_in[3];
    const float* b_proj = (const float*)d_in[4];
    float* out = (float*)d_out;

    static bool attr_set = false;
    if (!attr_set) {
        cudaFuncSetAttribute(gemm_qkv_tc,
            cudaFuncAttributeMaxDynamicSharedMemorySize, GEMM_SMEM_BYTES);
        cudaFuncSetAttribute(gemm_proj_tc,
            cudaFuncAttributeMaxDynamicSharedMemorySize, GEMM_SMEM_BYTES);
        cudaFuncSetAttribute(attn_tc_kernel,
            cudaFuncAttributeMaxDynamicSharedMemorySize, ATTN_SMEM_BYTES);
        attr_set = true;
    }

    preround_kernel<<<8448, 256>>>(x, w_attn, w_proj);
    gemm_qkv_tc<<<dim3(18, 64), 256, GEMM_SMEM_BYTES>>>(b_attn);
    attn_tc_kernel<<<dim3(16, 96), 256, ATTN_SMEM_BYTES>>>();
    gemm_proj_tc<<<dim3(6, 64), 256, GEMM_SMEM_BYTES>>>(b_proj, out);
}

// round 13
// speedup vs baseline: 2.6707x; 1.6843x over previous
#include <cuda_runtime.h>
#include <cuda_fp16.h>
#include <cstdint>

// Problem constants: B=8, T=1024, C=768, H=12, HD=64
// All scratch in fp16 (half) except softmax stats.
__device__ __half g_q[6291456];          // [96][1024][64]
__device__ __half g_k[6291456];
__device__ __half g_v[6291456];
__device__ __half g_y[6291456];          // [8192][768]
__device__ __half g_x[6291456];          // [8192][768]
__device__ uint32_t g_wa_p[884736];      // packed w_attn [k2=384][2304]
__device__ uint32_t g_wp_p[294912];      // packed w_proj [k2=384][768]

// ---------------------------------------------------------------------------
// helpers
// ---------------------------------------------------------------------------
__device__ __forceinline__ void mma_f16(float* c, const uint32_t* a, const uint32_t* b) {
    asm volatile(
        "mma.sync.aligned.m16n8k16.row.col.f32.f16.f16.f32 "
        "{%0,%1,%2,%3},{%4,%5,%6,%7},{%8,%9},{%0,%1,%2,%3};"
        : "+f"(c[0]), "+f"(c[1]), "+f"(c[2]), "+f"(c[3])
        : "r"(a[0]), "r"(a[1]), "r"(a[2]), "r"(a[3]), "r"(b[0]), "r"(b[1]));
}
__device__ __forceinline__ uint32_t smem_u32(const void* p) {
    return (uint32_t)__cvta_generic_to_shared(p);
}
__device__ __forceinline__ uint32_t packh2(float a, float b) {
    __half2 h = __floats2half2_rn(a, b);
    return *(uint32_t*)&h;
}
#define CP_ASYNC16(dst, src) \
    asm volatile("cp.async.cg.shared.global [%0], [%1], 16;\n" :: "r"(dst), "l"(src))
#define CP_COMMIT() asm volatile("cp.async.commit_group;\n")
#define CP_WAIT(N)  asm volatile("cp.async.wait_group %0;\n" :: "n"(N))

// ---------------------------------------------------------------------------
// Kernel 0a: x (float) -> g_x (half).
// ---------------------------------------------------------------------------
__global__ __launch_bounds__(256) void conv_x(const float* __restrict__ x)
{
    long i = (long)blockIdx.x * 256 + threadIdx.x;   // 1572864 float4s
    float4 v = ((const float4*)x)[i];
    uint2 o;
    o.x = packh2(v.x, v.y);
    o.y = packh2(v.z, v.w);
    ((uint2*)g_x)[i] = o;
}

// ---------------------------------------------------------------------------
// Kernel 0b: pack weights: dst[k2*N + n] = half2(w[2k2][n], w[2k2+1][n]).
// DEVICE-GLOBAL DESTINATION SELECTED IN-KERNEL (host must not pass the
// __device__ symbol as an argument -- that was the R11/R12 bug).
// ---------------------------------------------------------------------------
__global__ __launch_bounds__(256) void pack_w(
    const float* __restrict__ src, int N, int which)
{
    uint32_t* dst = which ? g_wp_p : g_wa_p;
    int idx = blockIdx.x * 256 + threadIdx.x;
    int k2 = idx / N, n = idx - k2 * N;
    float a = src[(size_t)(2 * k2) * N + n];
    float b = src[(size_t)(2 * k2 + 1) * N + n];
    dst[idx] = packh2(a, b);
}

// ---------------------------------------------------------------------------
// FP16 GEMM core: block tile 128x128, 8 warps (2m x 4n), warp tile 64x32,
// K-step 32 halfs (16 k-pairs), 24 steps, 3-stage cp.async, 1 sync/step.
//   As uint32 [3][128][20]  (A k-pairs)
//   Bs uint32 [3][16][136]  (B [k2][n])
// Dynamic smem 56832B; 2 CTAs/SM.
// ---------------------------------------------------------------------------
#define GEMM_SMEM_BYTES 56832

#define GEMMH_LOAD(S, CH, APTR, BPTR, LDB)                                      \
    _Pragma("unroll")                                                           \
    for (int i = 0; i < 2; i++) {                                               \
        int id = tid + i * 256;                                                 \
        int r = id >> 2, c = id & 3;                                            \
        CP_ASYNC16(smem_u32(&As[S][r][c * 4]),                                  \
                   (APTR) + (size_t)(m0 + r) * 768 + (CH) * 32 + c * 8);        \
    }                                                                           \
    _Pragma("unroll")                                                           \
    for (int i = 0; i < 2; i++) {                                               \
        int id = tid + i * 256;                                                 \
        int r = id >> 5, c = id & 31;                                           \
        CP_ASYNC16(smem_u32(&Bs[S][r][c * 4]),                                  \
                   (BPTR) + (size_t)((CH) * 16 + r) * (LDB) + n0 + c * 4);      \
    }                                                                           \
    CP_COMMIT();

#define GEMMH_BODY(APTR, BPTR, LDB)                                             \
    extern __shared__ char smem_raw[];                                          \
    uint32_t (*As)[128][20] = (uint32_t (*)[128][20])smem_raw;                  \
    uint32_t (*Bs)[16][136] = (uint32_t (*)[16][136])(smem_raw + 3 * 128 * 20 * 4); \
    const int tid  = threadIdx.x;                                               \
    const int lane = tid & 31;                                                  \
    const int wid  = tid >> 5;                                                  \
    const int warp_m = wid & 1, warp_n = wid >> 1;                              \
    const int g = lane >> 2, tg = lane & 3;                                     \
    const int m0 = blockIdx.y * 128, n0 = blockIdx.x * 128;                     \
    float acc[4][4][4] = {};                                                    \
    GEMMH_LOAD(0, 0, APTR, BPTR, LDB)                                           \
    GEMMH_LOAD(1, 1, APTR, BPTR, LDB)                                           \
    int sidx = 0, pidx = 2;                                                     \
    for (int step = 0; step < 24; step++) {                                     \
        if (step < 23) { CP_WAIT(1); } else { CP_WAIT(0); }                     \
        __syncthreads();                                                        \
        if (step + 2 < 24) {                                                    \
            GEMMH_LOAD(pidx, step + 2, APTR, BPTR, LDB)                         \
        }                                                                       \
        const int s = sidx;                                                     \
        _Pragma("unroll")                                                       \
        for (int ks = 0; ks < 2; ks++) {                                        \
            const int kk = ks * 8;                                              \
            uint32_t afr[4][4], bfr[4][2];                                      \
            _Pragma("unroll")                                                   \
            for (int mt = 0; mt < 4; mt++) {                                    \
                const int rb = warp_m * 64 + mt * 16;                           \
                afr[mt][0] = As[s][rb + g][kk + tg];                            \
                afr[mt][1] = As[s][rb + g + 8][kk + tg];                        \
                afr[mt][2] = As[s][rb + g][kk + tg + 4];                        \
                afr[mt][3] = As[s][rb + g + 8][kk + tg + 4];                    \
            }                                                                   \
            _Pragma("unroll")                                                   \
            for (int nt = 0; nt < 4; nt++) {                                    \
                const int cb = warp_n * 32 + nt * 8;                            \
                bfr[nt][0] = Bs[s][kk + tg][cb + g];                            \
                bfr[nt][1] = Bs[s][kk + tg + 4][cb + g];                        \
            }                                                                   \
            _Pragma("unroll")                                                   \
            for (int mt = 0; mt < 4; mt++)                                      \
                _Pragma("unroll")                                               \
                for (int nt = 0; nt < 4; nt++)                                  \
                    mma_f16(acc[mt][nt], afr[mt], bfr[nt]);                     \
        }                                                                       \
        sidx = (sidx == 2) ? 0 : sidx + 1;                                      \
        pidx = (pidx == 2) ? 0 : pidx + 1;                                      \
    }

// ---------------------------------------------------------------------------
// Kernel 1: QKV GEMM (M=8192, N=2304, K=768) -> q/k/v half [B,H,T,64].
// ---------------------------------------------------------------------------
__global__ __launch_bounds__(256, 2) void gemm_qkv_h(const float* __restrict__ bias)
{
    GEMMH_BODY(g_x, g_wa_p, 2304)

#pragma unroll
    for (int mt = 0; mt < 4; mt++) {
#pragma unroll
        for (int nt = 0; nt < 4; nt++) {
            int n = n0 + warp_n * 32 + nt * 8 + 2 * tg;   // even
            int which = n / 768;
            int c = n - which * 768;
            int hh = c >> 6, d = c & 63;
            uint32_t* dstp = (uint32_t*)((which == 0) ? g_q : (which == 1) ? g_k : g_v);
            float b0 = bias[n], b1 = bias[n + 1];
            int row0 = m0 + warp_m * 64 + mt * 16 + g;
            int bb = row0 >> 10, t0 = row0 & 1023;
            size_t base = ((((size_t)bb * 12 + hh) << 10) + t0) * 32 + (d >> 1);
            dstp[base]          = packh2(acc[mt][nt][0] + b0, acc[mt][nt][1] + b1);
            dstp[base + 8 * 32] = packh2(acc[mt][nt][2] + b0, acc[mt][nt][3] + b1);
        }
    }
}

// ---------------------------------------------------------------------------
// Kernel 3: projection (M=8192, N=768, K=768): g_y(half) @ wp -> fp32 out.
// ---------------------------------------------------------------------------
__global__ __launch_bounds__(256, 2) void gemm_proj_h(
    const float* __restrict__ bias, float* __restrict__ out)
{
    GEMMH_BODY(g_y, g_wp_p, 768)

#pragma unroll
    for (int mt = 0; mt < 4; mt++) {
#pragma unroll
        for (int nt = 0; nt < 4; nt++) {
            int n = n0 + warp_n * 32 + nt * 8 + 2 * tg;
            float b0 = bias[n], b1 = bias[n + 1];
            int row0 = m0 + warp_m * 64 + mt * 16 + g;
            *(float2*)(out + (size_t)row0 * 768 + n) =
                make_float2(acc[mt][nt][0] + b0, acc[mt][nt][1] + b1);
            *(float2*)(out + (size_t)(row0 + 8) * 768 + n) =
                make_float2(acc[mt][nt][2] + b0, acc[mt][nt][3] + b1);
        }
    }
}

// ---------------------------------------------------------------------------
// Kernel 2: causal flash attention, fp16 MMA / fp32 softmax.
// Grid (16, 96), 256 threads = 8 warps (4m x 2n).  Q tile 64 (regs),
// K/V tile 64.  Static smem ~45.8KB, 2 CTAs/SM.
//   Sf  fp32 scores [64][68]
//   Ks  uint32 [64][36]   K d-pairs (also Q staging)
//   Vp  uint32 [32][72]   V t-pairs
//   Pp  uint32 [64][36]   P half t-pairs
// ---------------------------------------------------------------------------
__global__ __launch_bounds__(256, 2) void attn_h_kernel()
{
    __shared__ float Sf[64][68];
    __shared__ uint32_t Ks[64][36];
    __shared__ uint32_t Vp[32][72];
    __shared__ uint32_t Pp[64][36];
    __shared__ float s_m[64], s_l[64], s_f[64];

    const int tid = threadIdx.x;
    const int lane = tid & 31;
    const int wid = tid >> 5;
    const int warp_m = wid & 3, warp_n = wid >> 2;
    const int g = lane >> 2, tg = lane & 3;
    const int qi = blockIdx.x, bh = blockIdx.y;
    const int q0 = qi * 64;
    const __half* qb = g_q + (size_t)bh * 65536;
    const __half* kb = g_k + (size_t)bh * 65536;
    const __half* vb = g_v + (size_t)bh * 65536;
    const int mr = warp_m * 16;

    // Stage Q (half) into Ks, hoist this warp's A-fragments, then Ks is free.
#pragma unroll
    for (int r = 0; r < 2; r++) {
        int id = tid + r * 256;
        int q = id >> 3, c = id & 7;
        *(uint4*)&Ks[q][c * 4] = *(const uint4*)(qb + (size_t)(q0 + q) * 64 + c * 8);
    }
    if (tid < 64) { s_m[tid] = -1e30f; s_l[tid] = 0.0f; }
    __syncthreads();

    uint32_t qfr[4][4];
#pragma unroll
    for (int ks = 0; ks < 4; ks++) {
        const int kk = ks * 8;
        qfr[ks][0] = Ks[mr + g][kk + tg];
        qfr[ks][1] = Ks[mr + g + 8][kk + tg];
        qfr[ks][2] = Ks[mr + g][kk + tg + 4];
        qfr[ks][3] = Ks[mr + g + 8][kk + tg + 4];
    }

    float acc_o[4][4] = {};

    const int ktiles = qi + 1;
    for (int kt = 0; kt < ktiles; kt++) {
        const int k0 = kt * 64;
        const bool diag = (kt == qi);

        __syncthreads();   // qfr hoisted / prior tile reads done
        // load K tile (d-pairs natural)
#pragma unroll
        for (int r = 0; r < 2; r++) {
            int id = tid + r * 256;
            int t = id >> 3, c = id & 7;
            *(uint4*)&Ks[t][c * 4] = *(const uint4*)(kb + (size_t)(k0 + t) * 64 + c * 8);
        }
        // load V tile, pack to t-pairs via byte_perm
#pragma unroll
        for (int j = 0; j < 4; j++) {
            int id = tid + j * 256;
            int i = id >> 5, d2 = id & 31;
            uint32_t r0 = *(const uint32_t*)(vb + (size_t)(k0 + 2 * i) * 64 + 2 * d2);
            uint32_t r1 = *(const uint32_t*)(vb + (size_t)(k0 + 2 * i + 1) * 64 + 2 * d2);
            Vp[i][2 * d2]     = __byte_perm(r0, r1, 0x5410);
            Vp[i][2 * d2 + 1] = __byte_perm(r0, r1, 0x7632);
        }
        __syncthreads();

        // ---- S = Q K^T ----
        float acc_s[4][4] = {};
#pragma unroll
        for (int ks = 0; ks < 4; ks++) {
            const int kk = ks * 8;
#pragma unroll
            for (int nt = 0; nt < 4; nt++) {
                const int nc = warp_n * 32 + nt * 8;
                uint32_t bfr[2];
                bfr[0] = Ks[nc + g][kk + tg];
                bfr[1] = Ks[nc + g][kk + tg + 4];
                mma_f16(acc_s[nt], qfr[ks], bfr);
            }
        }
        // mask + scale -> Sf (fp32)
#pragma unroll
        for (int nt = 0; nt < 4; nt++) {
            const int nc = warp_n * 32 + nt * 8;
#pragma unroll
            for (int e = 0; e < 4; e++) {
                int row = mr + g + (e >> 1) * 8;
                int col = nc + 2 * tg + (e & 1);
                float v = acc_s[nt][e] * 0.125f;
                if (diag && col > row) v = -1e30f;
                Sf[row][col] = v;
            }
        }
        __syncthreads();

        // ---- online softmax: 4 threads/row, write P as half t-pairs ----
        {
            const int row = tid >> 2, sub = tid & 3;
            float mold = s_m[row];
            float mt = mold;
            float vals[16];
#pragma unroll
            for (int j = 0; j < 16; j++) {
                vals[j] = Sf[row][sub * 16 + j];
                mt = fmaxf(mt, vals[j]);
            }
            mt = fmaxf(mt, __shfl_xor_sync(0xffffffffu, mt, 1));
            mt = fmaxf(mt, __shfl_xor_sync(0xffffffffu, mt, 2));
            float ls = 0.0f;
#pragma unroll
            for (int j = 0; j < 16; j++) {
                vals[j] = __expf(vals[j] - mt);
                ls += vals[j];
            }
#pragma unroll
            for (int j2 = 0; j2 < 8; j2++)
                Pp[row][sub * 8 + j2] = packh2(vals[2 * j2], vals[2 * j2 + 1]);
            ls += __shfl_xor_sync(0xffffffffu, ls, 1);
            ls += __shfl_xor_sync(0xffffffffu, ls, 2);
            if (sub == 0) {
                float f = __expf(mold - mt);
                s_m[row] = mt;
                s_l[row] = s_l[row] * f + ls;
                s_f[row] = f;
            }
        }
        __syncthreads();

        // ---- rescale O, accumulate P @ V ----
        float f0 = s_f[mr + g], f1 = s_f[mr + g + 8];
#pragma unroll
        for (int nt = 0; nt < 4; nt++) {
            acc_o[nt][0] *= f0; acc_o[nt][1] *= f0;
            acc_o[nt][2] *= f1; acc_o[nt][3] *= f1;
        }
#pragma unroll
        for (int ts = 0; ts < 4; ts++) {
            const int kk = ts * 8;
            uint32_t afr[4];
            afr[0] = Pp[mr + g][kk + tg];
            afr[1] = Pp[mr + g + 8][kk + tg];
            afr[2] = Pp[mr + g][kk + tg + 4];
            afr[3] = Pp[mr + g + 8][kk + tg + 4];
#pragma unroll
            for (int nt = 0; nt < 4; nt++) {
                const int nc = warp_n * 32 + nt * 8;
                uint32_t bfr[2];
                bfr[0] = Vp[kk + tg][nc + g];
                bfr[1] = Vp[kk + tg + 4][nc + g];
                mma_f16(acc_o[nt], afr, bfr);
            }
        }
    }

    // ---- epilogue: normalize, write g_y (half) in [B,T,C] layout ----
    const int b = bh / 12, h = bh - b * 12;
    float inv0 = 1.0f / s_l[mr + g];
    float inv1 = 1.0f / s_l[mr + g + 8];
    const int t0 = q0 + mr + g, t1 = t0 + 8;
#pragma unroll
    for (int nt = 0; nt < 4; nt++) {
        int col = warp_n * 32 + nt * 8 + 2 * tg;   // even
        uint32_t* d0 = (uint32_t*)(g_y + ((size_t)(b * 1024 + t0)) * 768 + h * 64 + col);
        uint32_t* d1 = (uint32_t*)(g_y + ((size_t)(b * 1024 + t1)) * 768 + h * 64 + col);
        *d0 = packh2(acc_o[nt][0] * inv0, acc_o[nt][1] * inv0);
        *d1 = packh2(acc_o[nt][2] * inv1, acc_o[nt][3] * inv1);
    }
}

// ---------------------------------------------------------------------------
extern "C" void kernel_launch(void* const* d_in, const int* in_sizes, int n_in,
                              void* d_out, int out_size)
{
    const float* x      = (const float*)d_in[0];
    const float* w_attn = (const float*)d_in[1];
    const float* b_attn = (const float*)d_in[2];
    const float* w_proj = (const float*)d_in[3];
    const float* b_proj = (const float*)d_in[4];
    float* out = (float*)d_out;

    static bool attr_set = false;
    if (!attr_set) {
        cudaFuncSetAttribute(gemm_qkv_h,
            cudaFuncAttributeMaxDynamicSharedMemorySize, GEMM_SMEM_BYTES);
        cudaFuncSetAttribute(gemm_proj_h,
            cudaFuncAttributeMaxDynamicSharedMemorySize, GEMM_SMEM_BYTES);
        attr_set = true;
    }

    conv_x<<<6144, 256>>>(x);
    pack_w<<<3456, 256>>>(w_attn, 2304, 0);
    pack_w<<<1152, 256>>>(w_proj, 768, 1);
    gemm_qkv_h<<<dim3(18, 64), 256, GEMM_SMEM_BYTES>>>(b_attn);
    attn_h_kernel<<<dim3(16, 96), 256>>>();
    gemm_proj_h<<<dim3(6, 64), 256, GEMM_SMEM_BYTES>>>(b_proj, out);
}